// round 14
// baseline (speedup 1.0000x reference)
#include <cuda_runtime.h>
#include <cstdint>

// Problem constants
#define BB   8
#define TT   2048
#define DD   1024
#define HH   4
#define HSZ  256
#define KC   4
#define UU   1365
#define UPAD 1376
#define BT   (BB*TT)       // 16384

#define SMS  36            // gemm smem K-stride
#define BUFE (128*SMS)
#define GEMM_SMEM (4*BUFE*4)

// per-step incoming bytes per consumer CTA: 8 producers x 2 warps x 144B bulk
#define SCAN_TX 2304u

// ---------------- scratch ----------------
__device__ float g_xn    [BT * DD];
__device__ float g_ifin  [BT * DD];
__device__ float g_lin_if[(size_t)BT * 2048];
__device__ float g_lin_zo[(size_t)BT * 2048];
__device__ float g_zn    [BT * DD];
__device__ float g_up    [(size_t)BT * 2730];
__device__ float g_act   [(size_t)BT * UPAD];
__device__ float g_dwpad [DD * UPAD];
__device__ float g_wif_r [2048 * DD];          // tf32-rounded weight copies
__device__ float g_wzo_r [2048 * DD];
__device__ float g_upw_r [2730 * DD];

__device__ __forceinline__ float tf32r(float f) {
    uint32_t r;
    asm("cvt.rna.tf32.f32 %0, %1;" : "=r"(r) : "f"(f));
    return __uint_as_float(r);
}

// ---------------- LayerNorm (tf32-rounded output) -----------------------------
__global__ void ln_kernel(const float* __restrict__ x,
                          const float* __restrict__ lnw,
                          const float* __restrict__ lnb,
                          float* __restrict__ xn) {
    int row = blockIdx.x;
    int tid = threadIdx.x;
    const float4* xr = (const float4*)(x + (size_t)row * DD);
    float4 v = xr[tid];
    float s1 = v.x + v.y + v.z + v.w;
    float s2 = v.x*v.x + v.y*v.y + v.z*v.z + v.w*v.w;
    for (int o = 16; o; o >>= 1) {
        s1 += __shfl_xor_sync(0xffffffffu, s1, o);
        s2 += __shfl_xor_sync(0xffffffffu, s2, o);
    }
    __shared__ float rs1[8], rs2[8];
    if ((tid & 31) == 0) { rs1[tid >> 5] = s1; rs2[tid >> 5] = s2; }
    __syncthreads();
    float t1 = 0.f, t2 = 0.f;
#pragma unroll
    for (int w = 0; w < 8; w++) { t1 += rs1[w]; t2 += rs2[w]; }
    float mean = t1 * (1.0f / DD);
    float var  = t2 * (1.0f / DD) - mean * mean;
    float rstd = rsqrtf(var + 1e-5f);
    float4 wv = ((const float4*)lnw)[tid];
    float4 bv = ((const float4*)lnb)[tid];
    float4 o4;
    o4.x = tf32r((v.x - mean) * rstd * wv.x + bv.x);
    o4.y = tf32r((v.y - mean) * rstd * wv.y + bv.y);
    o4.z = tf32r((v.z - mean) * rstd * wv.z + bv.z);
    o4.w = tf32r((v.w - mean) * rstd * wv.w + bv.w);
    ((float4*)(xn + (size_t)row * DD))[tid] = o4;
}

// ---------------- causal depthwise conv + swish (tf32-rounded) ----------------
__global__ void conv_kernel(const float* __restrict__ xn,
                            const float* __restrict__ convw,
                            const float* __restrict__ convb,
                            float* __restrict__ ifin) {
    int idx = blockIdx.x * blockDim.x + threadIdx.x;
    if (idx >= BT * DD) return;
    int c  = idx & (DD - 1);
    int bt = idx >> 10;
    int t  = bt & (TT - 1);
    int b  = bt >> 11;
    float4 w4 = ((const float4*)convw)[c];
    const float wk[4] = { w4.x, w4.y, w4.z, w4.w };
    float acc = convb[c];
#pragma unroll
    for (int k = 0; k < KC; k++) {
        int tt = t - 3 + k;
        float xv = (tt >= 0) ? xn[((size_t)(b * TT + tt) << 10) + c] : 0.f;
        acc = fmaf(wk[k], xv, acc);
    }
    ifin[idx] = tf32r(acc / (1.f + expf(-acc)));
}

// ---------------- weight prep: tf32 round-copy + padded down_w ----------------
__global__ void round_copy_kernel(const float* __restrict__ in,
                                  float* __restrict__ out, int n) {
    int idx = blockIdx.x * blockDim.x + threadIdx.x;
    if (idx < n) out[idx] = tf32r(in[idx]);
}

__global__ void pad_dw_kernel(const float* __restrict__ dw, float* __restrict__ out) {
    int idx = blockIdx.x * blockDim.x + threadIdx.x;
    if (idx >= DD * UPAD) return;
    int r = idx / UPAD, k = idx - r * UPAD;
    out[idx] = (k < UU) ? tf32r(dw[(size_t)r * UU + k]) : 0.f;
}

// ---------------- scan helpers ------------------------------------------------
__device__ __forceinline__ uint32_t smem_u32(const void* p) {
    return (uint32_t)__cvta_generic_to_shared(p);
}

__device__ __forceinline__ void mbar_init(uint32_t addr, uint32_t count) {
    asm volatile("mbarrier.init.shared.b64 [%0], %1;" :: "r"(addr), "r"(count) : "memory");
}

__device__ __forceinline__ void mbar_expect_tx(uint32_t addr, uint32_t bytes) {
    asm volatile("mbarrier.arrive.expect_tx.shared.b64 _, [%0], %1;"
                 :: "r"(addr), "r"(bytes) : "memory");
}

__device__ __forceinline__ uint32_t mapa_u32(uint32_t la, uint32_t peer) {
    uint32_t ra;
    asm("mapa.shared::cluster.u32 %0, %1, %2;" : "=r"(ra) : "r"(la), "r"(peer));
    return ra;
}

// bulk smem->peer-smem copy; tx-completion delivered to peer's mbarrier
__device__ __forceinline__ void bulk_to_peer(uint32_t ra_dst, uint32_t la_src,
                                             uint32_t bytes, uint32_t ra_mbar) {
    asm volatile(
        "cp.async.bulk.shared::cluster.shared::cta.mbarrier::complete_tx::bytes "
        "[%0], [%1], %2, [%3];"
        :: "r"(ra_dst), "r"(la_src), "r"(bytes), "r"(ra_mbar) : "memory");
}

__device__ __forceinline__ void wait_parity(uint32_t mbar, uint32_t parity) {
    asm volatile(
        "{\n\t.reg .pred P;\n\t"
        "WL_%=:\n\t"
        "mbarrier.try_wait.parity.acquire.cta.shared::cta.b64 P, [%0], %1, 0x989680;\n\t"
        "@P bra WD_%=;\n\t"
        "bra WL_%=;\n\t"
        "WD_%=:\n\t}"
        :: "r"(mbar), "r"(parity) : "memory");
}

__device__ __forceinline__ float tanh_fast(float x) {
    float y;
    asm("tanh.approx.f32 %0, %1;" : "=f"(y) : "f"(x));
    return y;
}

// packed dual-fp32 FMA: d = a*b + d (elementwise on {lo,hi})
__device__ __forceinline__ void fma_x2(uint64_t& d, uint64_t a, uint64_t b) {
    asm("fma.rn.f32x2 %0, %1, %2, %0;" : "+l"(d) : "l"(a), "l"(b));
}

// ---------------- recurrent scan: cluster-8, reg weights, BULK exchange ------
// R12 structure; exchange switched from 528 scalar st.async messages/step to
// 16 bulk copies/step (cp.async.bulk smem->peer-smem, 144B each). Each gate
// warp stages {32 h, s1, s2} contiguously, fences the async proxy, and lanes
// 0-7 issue one bulk per peer. Consumer reads inbox[parity][producer][batch].
__global__ void __launch_bounds__(256, 1) __cluster_dims__(8, 1, 1)
scan_kernel(const float* __restrict__ lin_if,
            const float* __restrict__ lin_zo,
            const float* __restrict__ whh,     // [H][1024][256]
            const float* __restrict__ bias,    // [H][1024]
            const float* __restrict__ gn_w,
            const float* __restrict__ gn_b,
            float* __restrict__ zn)
{
    int cl = blockIdx.x >> 3;
    int jj = blockIdx.x & 7;
    int h  = cl & 3;
    int q  = cl >> 2;

    int tid  = threadIdx.x;
    int r    = tid & 127;             // weight row within slice
    int half = tid >> 7;              // k-half
    int wrp  = tid >> 5, lane = tid & 31;

    // inbox[parity][producer jj][batch][0..31 h | 32 s1 | 33 s2 | 34,35 pad]
    __shared__ __align__(16) float inbox[2][8][2][36];
    __shared__ __align__(16) float stage[2][2][36];      // [parity][batch][36]
    __shared__ float part_sm[2][256];                    // [batch][tid]
    __shared__ __align__(8) uint64_t mbar[2];            // full[parity]

    // ---- weight slice into registers, packed as {w[2j], w[2j+1]} pairs ----
    uint64_t w2[64];
    {
        int gate = r >> 5, sl = r & 31;
        int rowg = gate * 256 + jj * 32 + sl;
        const float* src = whh + ((size_t)(h * 1024 + rowg)) * 256 + half * 128;
#pragma unroll
        for (int i = 0; i < 32; i++) {
            float4 v = *(const float4*)(src + 4 * i);
            w2[2*i]   = (uint64_t)__float_as_uint(v.x) | ((uint64_t)__float_as_uint(v.y) << 32);
            w2[2*i+1] = (uint64_t)__float_as_uint(v.z) | ((uint64_t)__float_as_uint(v.w) << 32);
        }
    }

    int s_loc = jj * 32 + lane;
    float gw = gn_w[h * HSZ + s_loc];
    float gb = gn_b[h * HSZ + s_loc];
    float bias_g[4];
#pragma unroll
    for (int g = 0; g < 4; g++) bias_g[g] = bias[h * 1024 + g * 256 + s_loc];

    // zero inbox (step-0 h state must be 0)
    for (int i = tid; i < 2 * 8 * 2 * 36; i += 256)
        ((float*)inbox)[i] = 0.f;
    uint32_t mb = smem_u32(mbar);
    if (tid == 0) {
        mbar_init(mb + 0, 1);
        mbar_init(mb + 8, 1);
        mbar_expect_tx(mb + 0, SCAN_TX);     // arm both parities for first uses
        mbar_expect_tx(mb + 8, SCAN_TX);
    }
    __syncthreads();
    // one-time cluster rendezvous: mbarriers armed + inbox zeroed everywhere
    asm volatile("barrier.cluster.arrive.aligned;" ::: "memory");
    asm volatile("barrier.cluster.wait.aligned;" ::: "memory");

    int ph0 = 0, ph1 = 0;
    float c_s = 0.f, n_s = 0.f, m_s = 0.f, h_prev = 0.f;

    int bw = (wrp < 2) ? wrp : 0;
    int bcur = 2 * q + bw;
    const float* lif = lin_if + (size_t)bcur * TT * 2048 + h * 512;
    const float* lzo = lin_zo + (size_t)bcur * TT * 2048 + h * 512;

    for (int t = 0; t < TT; t++) {
        int pb = t & 1, nb = pb ^ 1;

        // ---- gate-input prefetch (issues before the wait; hides under it) ----
        float pi = 0.f, pf = 0.f, pz = 0.f, po = 0.f;
        if (wrp < 2) {
            size_t off = (size_t)t * 2048;
            pi = lif[off + s_loc];
            pf = lif[off + 256 + s_loc];
            pz = lzo[off + s_loc];
            po = lzo[off + 256 + s_loc];
        }

        // ---- wait for all 8 producers' step t-1 data; re-arm; finalize ----
        if (t > 0) {
            if (pb == 0) {
                wait_parity(mb + 0, (uint32_t)ph0); ph0 ^= 1;
                if (tid == 0) mbar_expect_tx(mb + 0, SCAN_TX);
            } else {
                wait_parity(mb + 8, (uint32_t)ph1); ph1 ^= 1;
                if (tid == 0) mbar_expect_tx(mb + 8, SCAN_TX);
            }
            if (wrp < 2) {      // groupnorm finalize + zn store for step t-1
                float t1 = 0.f, t2 = 0.f;
#pragma unroll
                for (int p = 0; p < 8; p++) {
                    t1 += inbox[pb][p][bw][32];
                    t2 += inbox[pb][p][bw][33];
                }
                float mean = t1 * (1.0f / HSZ);
                float var  = t2 * (1.0f / HSZ) - mean * mean;
                float rstd = rsqrtf(var + 1e-5f);
                float znv  = tf32r((h_prev - mean) * rstd * gw + gb);
                zn[((size_t)(bcur * TT + (t - 1))) * DD + h * HSZ + s_loc] = znv;
            }
        }

        // ---- matvec over inbox[pb]: packed f32x2 FMAs, weights in regs ----
        // k = p*32 + sl; this thread covers producers pbase..pbase+3.
        int pbase = half * 4;
        uint64_t accA0 = 0ull, accA1 = 0ull;   // batch0
        uint64_t accB0 = 0ull, accB1 = 0ull;   // batch1
#pragma unroll
        for (int p = 0; p < 4; p++) {
            const float* h0p = &inbox[pb][pbase + p][0][0];
            const float* h1p = &inbox[pb][pbase + p][1][0];
#pragma unroll
            for (int sl = 0; sl < 32; sl += 4) {
                ulonglong2 h0 = *(const ulonglong2*)(h0p + sl);
                ulonglong2 h1 = *(const ulonglong2*)(h1p + sl);
                int wi = p * 16 + (sl >> 1);
                fma_x2(accA0, w2[wi],     h0.x);  fma_x2(accB0, w2[wi],     h1.x);
                fma_x2(accA1, w2[wi + 1], h0.y);  fma_x2(accB1, w2[wi + 1], h1.y);
            }
        }
        {
            float a_lo  = __uint_as_float((uint32_t)accA0);
            float a_hi  = __uint_as_float((uint32_t)(accA0 >> 32));
            float a_lo2 = __uint_as_float((uint32_t)accA1);
            float a_hi2 = __uint_as_float((uint32_t)(accA1 >> 32));
            part_sm[0][tid] = (a_lo + a_hi) + (a_lo2 + a_hi2);
            float b_lo  = __uint_as_float((uint32_t)accB0);
            float b_hi  = __uint_as_float((uint32_t)(accB0 >> 32));
            float b_lo2 = __uint_as_float((uint32_t)accB1);
            float b_hi2 = __uint_as_float((uint32_t)(accB1 >> 32));
            part_sm[1][tid] = (b_lo + b_hi) + (b_lo2 + b_hi2);
        }
        __syncthreads();                         // the ONLY per-step CTA sync

        // ---- gates + bulk push (warp0 = batch0, warp1 = batch1) ----
        if (wrp < 2) {
            float iv = part_sm[bw][lane]      + part_sm[bw][128 + lane]      + pi + bias_g[0];
            float fv = part_sm[bw][32 + lane] + part_sm[bw][160 + lane]      + pf + bias_g[1];
            float zv = part_sm[bw][64 + lane] + part_sm[bw][192 + lane]      + pz + bias_g[2];
            float ov = part_sm[bw][96 + lane] + part_sm[bw][224 + lane]      + po + bias_g[3];
            float zg = tanh_fast(zv);
            float og = 1.f / (1.f + __expf(-ov));
            float mn = fmaxf(fv + m_s, iv);
            float ie = __expf(iv - mn);
            float fe = __expf(fv + m_s - mn);
            c_s = fe * c_s + ie * zg;
            n_s = fe * n_s + ie;
            m_s = mn;
            float hval = og * (c_s / n_s);
            h_prev = hval;

            float s1 = hval, s2 = hval * hval;
#pragma unroll
            for (int o = 16; o; o >>= 1) {
                s1 += __shfl_xor_sync(0xffffffffu, s1, o);
                s2 += __shfl_xor_sync(0xffffffffu, s2, o);
            }

            // stage this warp's 144B block, then one bulk copy per peer
            stage[nb][bw][lane] = hval;
            if (lane == 0) { stage[nb][bw][32] = s1; stage[nb][bw][33] = s2; }
            __syncwarp();
            asm volatile("fence.proxy.async.shared::cta;" ::: "memory");
            if (lane < 8) {
                uint32_t peer   = (uint32_t)lane;
                uint32_t la_dst = smem_u32(&inbox[nb][jj][bw][0]);
                uint32_t la_src = smem_u32(&stage[nb][bw][0]);
                uint32_t la_m   = mb + (uint32_t)nb * 8u;
                uint32_t ra_dst = mapa_u32(la_dst, peer);
                uint32_t ra_m   = mapa_u32(la_m, peer);
                bulk_to_peer(ra_dst, la_src, 144u, ra_m);
            }
        }
    }

    // ---- finalize last step (pushes of t=TT-1 went to parity 0) ----
    wait_parity(mb + 0, (uint32_t)ph0);
    if (wrp < 2) {
        float t1 = 0.f, t2 = 0.f;
#pragma unroll
        for (int p = 0; p < 8; p++) {
            t1 += inbox[0][p][bw][32];
            t2 += inbox[0][p][bw][33];
        }
        float mean = t1 * (1.0f / HSZ);
        float var  = t2 * (1.0f / HSZ) - mean * mean;
        float rstd = rsqrtf(var + 1e-5f);
        float znv  = tf32r((h_prev - mean) * rstd * gw + gb);
        zn[((size_t)(bcur * TT + (TT - 1))) * DD + h * HSZ + s_loc] = znv;
    }
    // no CTA exits while peers may still target its SMEM
    asm volatile("barrier.cluster.arrive.aligned;" ::: "memory");
    asm volatile("barrier.cluster.wait.aligned;" ::: "memory");
}

// ================= tf32 tensor-core GEMM (pre-rounded operands) ===============
__device__ __forceinline__ void mma_tf32(float c[4], const uint32_t a[4],
                                         const uint32_t b[2]) {
    asm volatile(
        "mma.sync.aligned.m16n8k8.row.col.f32.tf32.tf32.f32 "
        "{%0,%1,%2,%3},{%4,%5,%6,%7},{%8,%9},{%0,%1,%2,%3};\n"
        : "+f"(c[0]), "+f"(c[1]), "+f"(c[2]), "+f"(c[3])
        : "r"(a[0]), "r"(a[1]), "r"(a[2]), "r"(a[3]), "r"(b[0]), "r"(b[1]));
}

__device__ __forceinline__ void cp16(uint32_t dst, const void* src, int srcsize) {
    asm volatile("cp.async.cg.shared.global [%0], [%1], 16, %2;\n"
                 :: "r"(dst), "l"(src), "r"(srcsize));
}

template <int MODE>
__global__ void __launch_bounds__(256) gemm_mma(
        const float* __restrict__ A, const float* __restrict__ W,
        float* __restrict__ C,
        int M, int N, int K, int lda, int ldw, int ldc,
        const float* __restrict__ bias, const float* __restrict__ resid)
{
    extern __shared__ float sm[];
    uint32_t sbase = (uint32_t)__cvta_generic_to_shared(sm);
    const uint32_t* Abuf[2] = { (const uint32_t*)sm,            (const uint32_t*)(sm + BUFE) };
    const uint32_t* Wbuf[2] = { (const uint32_t*)(sm + 2*BUFE), (const uint32_t*)(sm + 3*BUFE) };

    int tid  = threadIdx.x;
    int warp = tid >> 5, lane = tid & 31;
    int g = lane >> 2, tig = lane & 3;
    int wm = (warp >> 2) * 64;
    int wn = (warp & 3) * 32;
    int bm = blockIdx.x * 128;
    int bn = blockIdx.y * 128;

    float acc[4][4][4];
#pragma unroll
    for (int mt = 0; mt < 4; mt++)
#pragma unroll
        for (int nt = 0; nt < 4; nt++)
#pragma unroll
            for (int rr = 0; rr < 4; rr++) acc[mt][nt][rr] = 0.f;

    int KT = K >> 5;

    auto fill = [&](int kt, int buf) {
        int k0 = kt * 32;
        uint32_t sA = sbase + (uint32_t)(buf * BUFE) * 4u;
        uint32_t sW = sbase + (uint32_t)((2 + buf) * BUFE) * 4u;
#pragma unroll
        for (int i = 0; i < 4; i++) {
            int idx = tid + i * 256;
            int row = idx >> 3;
            int c4  = idx & 7;
            uint32_t soff = (uint32_t)(row * SMS + c4 * 4) * 4u;
            const float* srcA = A + (size_t)(bm + row) * lda + k0 + c4 * 4;
            cp16(sA + soff, srcA, 16);
            int wr = bn + row;
            const float* srcW = W + (size_t)(wr < N ? wr : 0) * ldw + k0 + c4 * 4;
            cp16(sW + soff, srcW, wr < N ? 16 : 0);
        }
        asm volatile("cp.async.commit_group;\n");
    };

    fill(0, 0);

    for (int kt = 0; kt < KT; kt++) {
        int buf = kt & 1;
        if (kt + 1 < KT) {
            fill(kt + 1, buf ^ 1);
            asm volatile("cp.async.wait_group 1;\n");
        } else {
            asm volatile("cp.async.wait_group 0;\n");
        }
        __syncthreads();

        const uint32_t* Ab = Abuf[buf];
        const uint32_t* Wb = Wbuf[buf];
#pragma unroll
        for (int ks = 0; ks < 4; ks++) {
            int k0 = ks * 8;
            uint32_t afr[4][4];
#pragma unroll
            for (int mt = 0; mt < 4; mt++) {
                const uint32_t* p = Ab + (wm + mt * 16 + g) * SMS + k0 + tig;
                afr[mt][0] = p[0];
                afr[mt][1] = p[8 * SMS];
                afr[mt][2] = p[4];
                afr[mt][3] = p[8 * SMS + 4];
            }
            uint32_t bfr[4][2];
#pragma unroll
            for (int nt = 0; nt < 4; nt++) {
                const uint32_t* p = Wb + (wn + nt * 8 + g) * SMS + k0 + tig;
                bfr[nt][0] = p[0];
                bfr[nt][1] = p[4];
            }
#pragma unroll
            for (int mt = 0; mt < 4; mt++)
#pragma unroll
                for (int nt = 0; nt < 4; nt++)
                    mma_tf32(acc[mt][nt], afr[mt], bfr[nt]);
        }
        __syncthreads();
    }

#pragma unroll
    for (int mt = 0; mt < 4; mt++) {
        int m0 = bm + wm + mt * 16 + g;
#pragma unroll
        for (int nt = 0; nt < 4; nt++) {
            int n0 = bn + wn + nt * 8 + 2 * tig;
            if (n0 < N) {
                float v0 = acc[mt][nt][0];
                float v1 = acc[mt][nt][1];
                float v2 = acc[mt][nt][2];
                float v3 = acc[mt][nt][3];
                if (MODE >= 1) {
                    float bz0 = bias[n0], bz1 = bias[n0 + 1];
                    v0 += bz0; v1 += bz1; v2 += bz0; v3 += bz1;
                }
                if (MODE == 2) {
                    v0 += resid[(size_t)m0 * ldc + n0];
                    v1 += resid[(size_t)m0 * ldc + n0 + 1];
                    v2 += resid[(size_t)(m0 + 8) * ldc + n0];
                    v3 += resid[(size_t)(m0 + 8) * ldc + n0 + 1];
                }
                C[(size_t)m0 * ldc + n0]           = v0;
                C[(size_t)m0 * ldc + n0 + 1]       = v1;
                C[(size_t)(m0 + 8) * ldc + n0]     = v2;
                C[(size_t)(m0 + 8) * ldc + n0 + 1] = v3;
            }
        }
    }
}

// ---------------- gelu(u1)*u2 (tf32-rounded output) ---------------------------
__global__ void act_kernel(const float* __restrict__ up, float* __restrict__ act) {
    int idx = blockIdx.x * blockDim.x + threadIdx.x;
    if (idx >= BT * UPAD) return;
    int row = idx / UPAD, j = idx - row * UPAD;
    float v = 0.f;
    if (j < UU) {
        float u1 = up[(size_t)row * 2730 + j];
        float u2 = up[(size_t)row * 2730 + UU + j];
        float th;
        asm("tanh.approx.f32 %0, %1;"
            : "=f"(th)
            : "f"(0.7978845608028654f * (u1 + 0.044715f * u1 * u1 * u1)));
        v = tf32r(0.5f * u1 * (1.f + th) * u2);
    }
    act[idx] = v;
}

// ---------------- launch ------------------------------------------------------
extern "C" void kernel_launch(void* const* d_in, const int* in_sizes, int n_in,
                              void* d_out, int out_size) {
    const float* x      = (const float*)d_in[0];
    const float* ln_w   = (const float*)d_in[1];
    const float* ln_b   = (const float*)d_in[2];
    const float* conv_w = (const float*)d_in[3];
    const float* conv_b = (const float*)d_in[4];
    const float* w_if   = (const float*)d_in[5];
    const float* w_zo   = (const float*)d_in[6];
    const float* w_hh   = (const float*)d_in[7];
    const float* bias   = (const float*)d_in[8];
    const float* gn_w   = (const float*)d_in[9];
    const float* gn_b   = (const float*)d_in[10];
    const float* up_w   = (const float*)d_in[11];
    const float* up_b   = (const float*)d_in[12];
    const float* down_w = (const float*)d_in[13];
    const float* down_b = (const float*)d_in[14];
    float* out = (float*)d_out;

    static float *p_xn = nullptr, *p_ifin, *p_lif, *p_lzo, *p_zn, *p_up, *p_act,
                 *p_dwpad, *p_wif, *p_wzo, *p_upw;
    if (!p_xn) {
        cudaGetSymbolAddress((void**)&p_xn,    g_xn);
        cudaGetSymbolAddress((void**)&p_ifin,  g_ifin);
        cudaGetSymbolAddress((void**)&p_lif,   g_lin_if);
        cudaGetSymbolAddress((void**)&p_lzo,   g_lin_zo);
        cudaGetSymbolAddress((void**)&p_zn,    g_zn);
        cudaGetSymbolAddress((void**)&p_up,    g_up);
        cudaGetSymbolAddress((void**)&p_act,   g_act);
        cudaGetSymbolAddress((void**)&p_dwpad, g_dwpad);
        cudaGetSymbolAddress((void**)&p_wif,   g_wif_r);
        cudaGetSymbolAddress((void**)&p_wzo,   g_wzo_r);
        cudaGetSymbolAddress((void**)&p_upw,   g_upw_r);
        cudaFuncSetAttribute(gemm_mma<0>,
            cudaFuncAttributeMaxDynamicSharedMemorySize, GEMM_SMEM);
        cudaFuncSetAttribute(gemm_mma<1>,
            cudaFuncAttributeMaxDynamicSharedMemorySize, GEMM_SMEM);
        cudaFuncSetAttribute(gemm_mma<2>,
            cudaFuncAttributeMaxDynamicSharedMemorySize, GEMM_SMEM);
    }

    ln_kernel  <<<BT, 256>>>(x, ln_w, ln_b, p_xn);                                  // 1
    conv_kernel<<<(BT * DD + 255) / 256, 256>>>(p_xn, conv_w, conv_b, p_ifin);      // 2
    round_copy_kernel<<<(2048 * DD + 255) / 256, 256>>>(w_if, p_wif, 2048 * DD);    // 3
    round_copy_kernel<<<(2048 * DD + 255) / 256, 256>>>(w_zo, p_wzo, 2048 * DD);    // 4
    round_copy_kernel<<<(2730 * DD + 255) / 256, 256>>>(up_w, p_upw, 2730 * DD);    // 5
    gemm_mma<0><<<dim3(BT / 128, 2048 / 128), 256, GEMM_SMEM>>>(                    // 6
        p_ifin, p_wif, p_lif, BT, 2048, 1024, 1024, 1024, 2048, nullptr, nullptr);
    gemm_mma<0><<<dim3(BT / 128, 2048 / 128), 256, GEMM_SMEM>>>(                    // 7
        p_xn, p_wzo, p_lzo, BT, 2048, 1024, 1024, 1024, 2048, nullptr, nullptr);
    pad_dw_kernel<<<(DD * UPAD + 255) / 256, 256>>>(down_w, p_dwpad);               // 8
    scan_kernel<<<128, 256>>>(p_lif, p_lzo, w_hh, bias, gn_w, gn_b, p_zn);          // 9
    gemm_mma<1><<<dim3(BT / 128, (2730 + 127) / 128), 256, GEMM_SMEM>>>(            // 10
        p_zn, p_upw, p_up, BT, 2730, 1024, 1024, 1024, 2730, up_b, nullptr);
    act_kernel<<<(BT * UPAD + 255) / 256, 256>>>(p_up, p_act);                      // 11
    gemm_mma<2><<<dim3(BT / 128, 1024 / 128), 256, GEMM_SMEM>>>(                    // 12
        p_act, p_dwpad, out, BT, 1024, UPAD, UPAD, UPAD, 1024, down_b, x);
}

// round 15
// speedup vs baseline: 1.1442x; 1.1442x over previous
#include <cuda_runtime.h>
#include <cstdint>

// Problem constants
#define BB   8
#define TT   2048
#define DD   1024
#define HH   4
#define HSZ  256
#define KC   4
#define UU   1365
#define UPAD 1376
#define BT   (BB*TT)       // 16384

#define SMS  36            // gemm smem K-stride
#define BUFE (128*SMS)
#define GEMM_SMEM (4*BUFE*4)

// per-step incoming bytes per consumer CTA (st.async tx accounting)
#define SCAN_TX 2176u

// ---------------- scratch ----------------
__device__ float g_xn    [BT * DD];
__device__ float g_ifin  [BT * DD];
__device__ float g_lin_if[(size_t)BT * 2048];
__device__ float g_lin_zo[(size_t)BT * 2048];
__device__ float g_zn    [BT * DD];
__device__ float g_up    [(size_t)BT * 2730];
__device__ float g_act   [(size_t)BT * UPAD];
__device__ float g_dwpad [DD * UPAD];
__device__ float g_wif_r [2048 * DD];          // tf32-rounded weight copies
__device__ float g_wzo_r [2048 * DD];
__device__ float g_upw_r [2730 * DD];

__device__ __forceinline__ float tf32r(float f) {
    uint32_t r;
    asm("cvt.rna.tf32.f32 %0, %1;" : "=r"(r) : "f"(f));
    return __uint_as_float(r);
}

// ---------------- LayerNorm (tf32-rounded output) -----------------------------
__global__ void ln_kernel(const float* __restrict__ x,
                          const float* __restrict__ lnw,
                          const float* __restrict__ lnb,
                          float* __restrict__ xn) {
    int row = blockIdx.x;
    int tid = threadIdx.x;
    const float4* xr = (const float4*)(x + (size_t)row * DD);
    float4 v = xr[tid];
    float s1 = v.x + v.y + v.z + v.w;
    float s2 = v.x*v.x + v.y*v.y + v.z*v.z + v.w*v.w;
    for (int o = 16; o; o >>= 1) {
        s1 += __shfl_xor_sync(0xffffffffu, s1, o);
        s2 += __shfl_xor_sync(0xffffffffu, s2, o);
    }
    __shared__ float rs1[8], rs2[8];
    if ((tid & 31) == 0) { rs1[tid >> 5] = s1; rs2[tid >> 5] = s2; }
    __syncthreads();
    float t1 = 0.f, t2 = 0.f;
#pragma unroll
    for (int w = 0; w < 8; w++) { t1 += rs1[w]; t2 += rs2[w]; }
    float mean = t1 * (1.0f / DD);
    float var  = t2 * (1.0f / DD) - mean * mean;
    float rstd = rsqrtf(var + 1e-5f);
    float4 wv = ((const float4*)lnw)[tid];
    float4 bv = ((const float4*)lnb)[tid];
    float4 o4;
    o4.x = tf32r((v.x - mean) * rstd * wv.x + bv.x);
    o4.y = tf32r((v.y - mean) * rstd * wv.y + bv.y);
    o4.z = tf32r((v.z - mean) * rstd * wv.z + bv.z);
    o4.w = tf32r((v.w - mean) * rstd * wv.w + bv.w);
    ((float4*)(xn + (size_t)row * DD))[tid] = o4;
}

// ---------------- causal depthwise conv + swish (tf32-rounded) ----------------
__global__ void conv_kernel(const float* __restrict__ xn,
                            const float* __restrict__ convw,
                            const float* __restrict__ convb,
                            float* __restrict__ ifin) {
    int idx = blockIdx.x * blockDim.x + threadIdx.x;
    if (idx >= BT * DD) return;
    int c  = idx & (DD - 1);
    int bt = idx >> 10;
    int t  = bt & (TT - 1);
    int b  = bt >> 11;
    float4 w4 = ((const float4*)convw)[c];
    const float wk[4] = { w4.x, w4.y, w4.z, w4.w };
    float acc = convb[c];
#pragma unroll
    for (int k = 0; k < KC; k++) {
        int tt = t - 3 + k;
        float xv = (tt >= 0) ? xn[((size_t)(b * TT + tt) << 10) + c] : 0.f;
        acc = fmaf(wk[k], xv, acc);
    }
    ifin[idx] = tf32r(acc / (1.f + expf(-acc)));
}

// ---------------- weight prep: tf32 round-copy + padded down_w ----------------
__global__ void round_copy_kernel(const float* __restrict__ in,
                                  float* __restrict__ out, int n) {
    int idx = blockIdx.x * blockDim.x + threadIdx.x;
    if (idx < n) out[idx] = tf32r(in[idx]);
}

__global__ void pad_dw_kernel(const float* __restrict__ dw, float* __restrict__ out) {
    int idx = blockIdx.x * blockDim.x + threadIdx.x;
    if (idx >= DD * UPAD) return;
    int r = idx / UPAD, k = idx - r * UPAD;
    out[idx] = (k < UU) ? tf32r(dw[(size_t)r * UU + k]) : 0.f;
}

// ---------------- scan helpers ------------------------------------------------
__device__ __forceinline__ uint32_t smem_u32(const void* p) {
    return (uint32_t)__cvta_generic_to_shared(p);
}

__device__ __forceinline__ void mbar_init(uint32_t addr, uint32_t count) {
    asm volatile("mbarrier.init.shared.b64 [%0], %1;" :: "r"(addr), "r"(count) : "memory");
}

__device__ __forceinline__ void mbar_expect_tx(uint32_t addr, uint32_t bytes) {
    asm volatile("mbarrier.arrive.expect_tx.shared.b64 _, [%0], %1;"
                 :: "r"(addr), "r"(bytes) : "memory");
}

__device__ __forceinline__ uint32_t mapa_u32(uint32_t la, uint32_t peer) {
    uint32_t ra;
    asm("mapa.shared::cluster.u32 %0, %1, %2;" : "=r"(ra) : "r"(la), "r"(peer));
    return ra;
}

__device__ __forceinline__ void st_async_b32(uint32_t raddr, uint32_t v, uint32_t rmbar) {
    asm volatile("st.async.shared::cluster.mbarrier::complete_tx::bytes.b32 [%0], %1, [%2];"
                 :: "r"(raddr), "r"(v), "r"(rmbar) : "memory");
}
__device__ __forceinline__ void st_async_b64(uint32_t raddr, uint64_t v, uint32_t rmbar) {
    asm volatile("st.async.shared::cluster.mbarrier::complete_tx::bytes.b64 [%0], %1, [%2];"
                 :: "r"(raddr), "l"(v), "r"(rmbar) : "memory");
}

__device__ __forceinline__ void wait_parity(uint32_t mbar, uint32_t parity) {
    asm volatile(
        "{\n\t.reg .pred P;\n\t"
        "WL_%=:\n\t"
        "mbarrier.try_wait.parity.acquire.cta.shared::cta.b64 P, [%0], %1, 0x989680;\n\t"
        "@P bra WD_%=;\n\t"
        "bra WL_%=;\n\t"
        "WD_%=:\n\t}"
        :: "r"(mbar), "r"(parity) : "memory");
}

__device__ __forceinline__ float tanh_fast(float x) {
    float y;
    asm("tanh.approx.f32 %0, %1;" : "=f"(y) : "f"(x));
    return y;
}

// packed dual-fp32 FMA: d = a*b + d (elementwise on {lo,hi})
__device__ __forceinline__ void fma_x2(uint64_t& d, uint64_t a, uint64_t b) {
    asm("fma.rn.f32x2 %0, %1, %2, %0;" : "+l"(d) : "l"(a), "l"(b));
}

// ---------------- recurrent scan: cluster-8, reg weights, st.async exchange ---
// (byte-identical to the R12 6974us winner: f32x2 matvec, scalar st.async)
__global__ void __launch_bounds__(256, 1) __cluster_dims__(8, 1, 1)
scan_kernel(const float* __restrict__ lin_if,
            const float* __restrict__ lin_zo,
            const float* __restrict__ whh,     // [H][1024][256]
            const float* __restrict__ bias,    // [H][1024]
            const float* __restrict__ gn_w,
            const float* __restrict__ gn_b,
            float* __restrict__ zn)
{
    int cl = blockIdx.x >> 3;
    int jj = blockIdx.x & 7;
    int h  = cl & 3;
    int q  = cl >> 2;

    int tid  = threadIdx.x;
    int r    = tid & 127;             // weight row within slice
    int half = tid >> 7;              // k-half
    int wrp  = tid >> 5, lane = tid & 31;

    __shared__ __align__(16) float hbuf[2][2][256];      // [parity][batch][k]
    __shared__ __align__(8)  float sumbuf[2][2][8][2];   // [parity][batch][jj][s1,s2]
    __shared__ float part_sm[2][256];                    // [batch][tid]
    __shared__ __align__(8) uint64_t mbar[2];            // full[parity]

    // ---- weight slice into registers, packed as {w[2j], w[2j+1]} pairs ----
    uint64_t w2[64];
    {
        int gate = r >> 5, sl = r & 31;
        int rowg = gate * 256 + jj * 32 + sl;
        const float* src = whh + ((size_t)(h * 1024 + rowg)) * 256 + half * 128;
#pragma unroll
        for (int i = 0; i < 32; i++) {
            float4 v = *(const float4*)(src + 4 * i);
            w2[2*i]   = (uint64_t)__float_as_uint(v.x) | ((uint64_t)__float_as_uint(v.y) << 32);
            w2[2*i+1] = (uint64_t)__float_as_uint(v.z) | ((uint64_t)__float_as_uint(v.w) << 32);
        }
    }

    int s_loc = jj * 32 + lane;
    float gw = gn_w[h * HSZ + s_loc];
    float gb = gn_b[h * HSZ + s_loc];
    float bias_g[4];
#pragma unroll
    for (int g = 0; g < 4; g++) bias_g[g] = bias[h * 1024 + g * 256 + s_loc];

    hbuf[0][0][tid] = 0.f;
    hbuf[0][1][tid] = 0.f;
    uint32_t mb = smem_u32(mbar);
    if (tid == 0) {
        mbar_init(mb + 0, 1);
        mbar_init(mb + 8, 1);
        mbar_expect_tx(mb + 0, SCAN_TX);     // arm both parities for first uses
        mbar_expect_tx(mb + 8, SCAN_TX);
    }
    __syncthreads();
    // one-time cluster rendezvous: mbarriers armed + hbuf zeroed everywhere
    asm volatile("barrier.cluster.arrive.aligned;" ::: "memory");
    asm volatile("barrier.cluster.wait.aligned;" ::: "memory");

    int ph0 = 0, ph1 = 0;
    float c_s = 0.f, n_s = 0.f, m_s = 0.f, h_prev = 0.f;

    int bw = (wrp < 2) ? wrp : 0;
    int bcur = 2 * q + bw;
    const float* lif = lin_if + (size_t)bcur * TT * 2048 + h * 512;
    const float* lzo = lin_zo + (size_t)bcur * TT * 2048 + h * 512;

    for (int t = 0; t < TT; t++) {
        int pb = t & 1, nb = pb ^ 1;

        // ---- gate-input prefetch (issues before the wait; hides under it) ----
        float pi = 0.f, pf = 0.f, pz = 0.f, po = 0.f;
        if (wrp < 2) {
            size_t off = (size_t)t * 2048;
            pi = lif[off + s_loc];
            pf = lif[off + 256 + s_loc];
            pz = lzo[off + s_loc];
            po = lzo[off + 256 + s_loc];
        }

        // ---- wait for all 8 producers' step t-1 data; re-arm; finalize ----
        if (t > 0) {
            if (pb == 0) {
                wait_parity(mb + 0, (uint32_t)ph0); ph0 ^= 1;
                if (tid == 0) mbar_expect_tx(mb + 0, SCAN_TX);
            } else {
                wait_parity(mb + 8, (uint32_t)ph1); ph1 ^= 1;
                if (tid == 0) mbar_expect_tx(mb + 8, SCAN_TX);
            }
            if (wrp < 2) {      // groupnorm finalize + zn store for step t-1
                float t1 = 0.f, t2 = 0.f;
#pragma unroll
                for (int p = 0; p < 8; p++) {
                    t1 += sumbuf[pb][bw][p][0];
                    t2 += sumbuf[pb][bw][p][1];
                }
                float mean = t1 * (1.0f / HSZ);
                float var  = t2 * (1.0f / HSZ) - mean * mean;
                float rstd = rsqrtf(var + 1e-5f);
                float znv  = tf32r((h_prev - mean) * rstd * gw + gb);
                zn[((size_t)(bcur * TT + (t - 1))) * DD + h * HSZ + s_loc] = znv;
            }
        }

        // ---- matvec over hbuf[pb]: packed f32x2 FMAs, weights in regs ----
        int kbase = half * 128;
        uint64_t accA0 = 0ull, accA1 = 0ull;   // batch0 (two independent chains)
        uint64_t accB0 = 0ull, accB1 = 0ull;   // batch1
#pragma unroll
        for (int kk = 0; kk < 128; kk += 4) {
            ulonglong2 h0 = *(const ulonglong2*)&hbuf[pb][0][kbase + kk];
            ulonglong2 h1 = *(const ulonglong2*)&hbuf[pb][1][kbase + kk];
            uint64_t wa = w2[kk >> 1], wb = w2[(kk >> 1) + 1];
            fma_x2(accA0, wa, h0.x);  fma_x2(accB0, wa, h1.x);
            fma_x2(accA1, wb, h0.y);  fma_x2(accB1, wb, h1.y);
        }
        {
            float a_lo  = __uint_as_float((uint32_t)accA0);
            float a_hi  = __uint_as_float((uint32_t)(accA0 >> 32));
            float a_lo2 = __uint_as_float((uint32_t)accA1);
            float a_hi2 = __uint_as_float((uint32_t)(accA1 >> 32));
            part_sm[0][tid] = (a_lo + a_hi) + (a_lo2 + a_hi2);
            float b_lo  = __uint_as_float((uint32_t)accB0);
            float b_hi  = __uint_as_float((uint32_t)(accB0 >> 32));
            float b_lo2 = __uint_as_float((uint32_t)accB1);
            float b_hi2 = __uint_as_float((uint32_t)(accB1 >> 32));
            part_sm[1][tid] = (b_lo + b_hi) + (b_lo2 + b_hi2);
        }
        __syncthreads();                         // the ONLY per-step CTA sync

        // ---- gates + push (warp0 = batch0, warp1 = batch1) ----
        if (wrp < 2) {
            float iv = part_sm[bw][lane]      + part_sm[bw][128 + lane]      + pi + bias_g[0];
            float fv = part_sm[bw][32 + lane] + part_sm[bw][160 + lane]      + pf + bias_g[1];
            float zv = part_sm[bw][64 + lane] + part_sm[bw][192 + lane]      + pz + bias_g[2];
            float ov = part_sm[bw][96 + lane] + part_sm[bw][224 + lane]      + po + bias_g[3];
            float zg = tanh_fast(zv);
            float og = 1.f / (1.f + __expf(-ov));
            float mn = fmaxf(fv + m_s, iv);
            float ie = __expf(iv - mn);
            float fe = __expf(fv + m_s - mn);
            c_s = fe * c_s + ie * zg;
            n_s = fe * n_s + ie;
            m_s = mn;
            float hval = og * (c_s / n_s);
            h_prev = hval;

            float s1 = hval, s2 = hval * hval;
#pragma unroll
            for (int o = 16; o; o >>= 1) {
                s1 += __shfl_xor_sync(0xffffffffu, s1, o);
                s2 += __shfl_xor_sync(0xffffffffu, s2, o);
            }

            // push h(t) to all 8 peers (self included) via st.async
            uint32_t hb   = __float_as_uint(hval);
            uint32_t la_h = smem_u32(&hbuf[nb][bw][s_loc]);
            uint32_t la_m = mb + (uint32_t)nb * 8u;
#pragma unroll
            for (uint32_t peer = 0; peer < 8; peer++) {
                uint32_t ra_h = mapa_u32(la_h, peer);
                uint32_t ra_m = mapa_u32(la_m, peer);
                st_async_b32(ra_h, hb, ra_m);
            }
            if (lane == 0) {
                uint64_t spk;
                asm("mov.b64 %0, {%1,%2};" : "=l"(spk) : "f"(s1), "f"(s2));
                uint32_t la_s = smem_u32(&sumbuf[nb][bw][jj][0]);
#pragma unroll
                for (uint32_t peer = 0; peer < 8; peer++) {
                    uint32_t ra_s = mapa_u32(la_s, peer);
                    uint32_t ra_m = mapa_u32(la_m, peer);
                    st_async_b64(ra_s, spk, ra_m);
                }
            }
        }
    }

    // ---- finalize last step (pushes of t=TT-1 went to parity 0) ----
    wait_parity(mb + 0, (uint32_t)ph0);
    if (wrp < 2) {
        float t1 = 0.f, t2 = 0.f;
#pragma unroll
        for (int p = 0; p < 8; p++) {
            t1 += sumbuf[0][bw][p][0];
            t2 += sumbuf[0][bw][p][1];
        }
        float mean = t1 * (1.0f / HSZ);
        float var  = t2 * (1.0f / HSZ) - mean * mean;
        float rstd = rsqrtf(var + 1e-5f);
        float znv  = tf32r((h_prev - mean) * rstd * gw + gb);
        zn[((size_t)(bcur * TT + (TT - 1))) * DD + h * HSZ + s_loc] = znv;
    }
    // no CTA exits while peers may still target its SMEM
    asm volatile("barrier.cluster.arrive.aligned;" ::: "memory");
    asm volatile("barrier.cluster.wait.aligned;" ::: "memory");
}

// ================= tf32 tensor-core GEMM (pre-rounded operands) ===============
// Single change this round: __launch_bounds__(256, 2) — with the cvts gone
// since R8 the mainloop live set should fit 128 regs without spills, giving
// 2 CTAs/SM (4 warps/SMSP) to hide the LDS->HMMA latency that keeps issue at 31%.
__device__ __forceinline__ void mma_tf32(float c[4], const uint32_t a[4],
                                         const uint32_t b[2]) {
    asm volatile(
        "mma.sync.aligned.m16n8k8.row.col.f32.tf32.tf32.f32 "
        "{%0,%1,%2,%3},{%4,%5,%6,%7},{%8,%9},{%0,%1,%2,%3};\n"
        : "+f"(c[0]), "+f"(c[1]), "+f"(c[2]), "+f"(c[3])
        : "r"(a[0]), "r"(a[1]), "r"(a[2]), "r"(a[3]), "r"(b[0]), "r"(b[1]));
}

__device__ __forceinline__ void cp16(uint32_t dst, const void* src, int srcsize) {
    asm volatile("cp.async.cg.shared.global [%0], [%1], 16, %2;\n"
                 :: "r"(dst), "l"(src), "r"(srcsize));
}

template <int MODE>
__global__ void __launch_bounds__(256, 2) gemm_mma(
        const float* __restrict__ A, const float* __restrict__ W,
        float* __restrict__ C,
        int M, int N, int K, int lda, int ldw, int ldc,
        const float* __restrict__ bias, const float* __restrict__ resid)
{
    extern __shared__ float sm[];
    uint32_t sbase = (uint32_t)__cvta_generic_to_shared(sm);
    const uint32_t* Abuf[2] = { (const uint32_t*)sm,            (const uint32_t*)(sm + BUFE) };
    const uint32_t* Wbuf[2] = { (const uint32_t*)(sm + 2*BUFE), (const uint32_t*)(sm + 3*BUFE) };

    int tid  = threadIdx.x;
    int warp = tid >> 5, lane = tid & 31;
    int g = lane >> 2, tig = lane & 3;
    int wm = (warp >> 2) * 64;
    int wn = (warp & 3) * 32;
    int bm = blockIdx.x * 128;
    int bn = blockIdx.y * 128;

    float acc[4][4][4];
#pragma unroll
    for (int mt = 0; mt < 4; mt++)
#pragma unroll
        for (int nt = 0; nt < 4; nt++)
#pragma unroll
            for (int rr = 0; rr < 4; rr++) acc[mt][nt][rr] = 0.f;

    int KT = K >> 5;

    auto fill = [&](int kt, int buf) {
        int k0 = kt * 32;
        uint32_t sA = sbase + (uint32_t)(buf * BUFE) * 4u;
        uint32_t sW = sbase + (uint32_t)((2 + buf) * BUFE) * 4u;
#pragma unroll
        for (int i = 0; i < 4; i++) {
            int idx = tid + i * 256;
            int row = idx >> 3;
            int c4  = idx & 7;
            uint32_t soff = (uint32_t)(row * SMS + c4 * 4) * 4u;
            const float* srcA = A + (size_t)(bm + row) * lda + k0 + c4 * 4;
            cp16(sA + soff, srcA, 16);
            int wr = bn + row;
            const float* srcW = W + (size_t)(wr < N ? wr : 0) * ldw + k0 + c4 * 4;
            cp16(sW + soff, srcW, wr < N ? 16 : 0);
        }
        asm volatile("cp.async.commit_group;\n");
    };

    fill(0, 0);

    for (int kt = 0; kt < KT; kt++) {
        int buf = kt & 1;
        if (kt + 1 < KT) {
            fill(kt + 1, buf ^ 1);
            asm volatile("cp.async.wait_group 1;\n");
        } else {
            asm volatile("cp.async.wait_group 0;\n");
        }
        __syncthreads();

        const uint32_t* Ab = Abuf[buf];
        const uint32_t* Wb = Wbuf[buf];
#pragma unroll
        for (int ks = 0; ks < 4; ks++) {
            int k0 = ks * 8;
            uint32_t afr[4][4];
#pragma unroll
            for (int mt = 0; mt < 4; mt++) {
                const uint32_t* p = Ab + (wm + mt * 16 + g) * SMS + k0 + tig;
                afr[mt][0] = p[0];
                afr[mt][1] = p[8 * SMS];
                afr[mt][2] = p[4];
                afr[mt][3] = p[8 * SMS + 4];
            }
            uint32_t bfr[4][2];
#pragma unroll
            for (int nt = 0; nt < 4; nt++) {
                const uint32_t* p = Wb + (wn + nt * 8 + g) * SMS + k0 + tig;
                bfr[nt][0] = p[0];
                bfr[nt][1] = p[4];
            }
#pragma unroll
            for (int mt = 0; mt < 4; mt++)
#pragma unroll
                for (int nt = 0; nt < 4; nt++)
                    mma_tf32(acc[mt][nt], afr[mt], bfr[nt]);
        }
        __syncthreads();
    }

#pragma unroll
    for (int mt = 0; mt < 4; mt++) {
        int m0 = bm + wm + mt * 16 + g;
#pragma unroll
        for (int nt = 0; nt < 4; nt++) {
            int n0 = bn + wn + nt * 8 + 2 * tig;
            if (n0 < N) {
                float v0 = acc[mt][nt][0];
                float v1 = acc[mt][nt][1];
                float v2 = acc[mt][nt][2];
                float v3 = acc[mt][nt][3];
                if (MODE >= 1) {
                    float bz0 = bias[n0], bz1 = bias[n0 + 1];
                    v0 += bz0; v1 += bz1; v2 += bz0; v3 += bz1;
                }
                if (MODE == 2) {
                    v0 += resid[(size_t)m0 * ldc + n0];
                    v1 += resid[(size_t)m0 * ldc + n0 + 1];
                    v2 += resid[(size_t)(m0 + 8) * ldc + n0];
                    v3 += resid[(size_t)(m0 + 8) * ldc + n0 + 1];
                }
                C[(size_t)m0 * ldc + n0]           = v0;
                C[(size_t)m0 * ldc + n0 + 1]       = v1;
                C[(size_t)(m0 + 8) * ldc + n0]     = v2;
                C[(size_t)(m0 + 8) * ldc + n0 + 1] = v3;
            }
        }
    }
}

// ---------------- gelu(u1)*u2 (tf32-rounded output) ---------------------------
__global__ void act_kernel(const float* __restrict__ up, float* __restrict__ act) {
    int idx = blockIdx.x * blockDim.x + threadIdx.x;
    if (idx >= BT * UPAD) return;
    int row = idx / UPAD, j = idx - row * UPAD;
    float v = 0.f;
    if (j < UU) {
        float u1 = up[(size_t)row * 2730 + j];
        float u2 = up[(size_t)row * 2730 + UU + j];
        float th;
        asm("tanh.approx.f32 %0, %1;"
            : "=f"(th)
            : "f"(0.7978845608028654f * (u1 + 0.044715f * u1 * u1 * u1)));
        v = tf32r(0.5f * u1 * (1.f + th) * u2);
    }
    act[idx] = v;
}

// ---------------- launch ------------------------------------------------------
extern "C" void kernel_launch(void* const* d_in, const int* in_sizes, int n_in,
                              void* d_out, int out_size) {
    const float* x      = (const float*)d_in[0];
    const float* ln_w   = (const float*)d_in[1];
    const float* ln_b   = (const float*)d_in[2];
    const float* conv_w = (const float*)d_in[3];
    const float* conv_b = (const float*)d_in[4];
    const float* w_if   = (const float*)d_in[5];
    const float* w_zo   = (const float*)d_in[6];
    const float* w_hh   = (const float*)d_in[7];
    const float* bias   = (const float*)d_in[8];
    const float* gn_w   = (const float*)d_in[9];
    const float* gn_b   = (const float*)d_in[10];
    const float* up_w   = (const float*)d_in[11];
    const float* up_b   = (const float*)d_in[12];
    const float* down_w = (const float*)d_in[13];
    const float* down_b = (const float*)d_in[14];
    float* out = (float*)d_out;

    static float *p_xn = nullptr, *p_ifin, *p_lif, *p_lzo, *p_zn, *p_up, *p_act,
                 *p_dwpad, *p_wif, *p_wzo, *p_upw;
    if (!p_xn) {
        cudaGetSymbolAddress((void**)&p_xn,    g_xn);
        cudaGetSymbolAddress((void**)&p_ifin,  g_ifin);
        cudaGetSymbolAddress((void**)&p_lif,   g_lin_if);
        cudaGetSymbolAddress((void**)&p_lzo,   g_lin_zo);
        cudaGetSymbolAddress((void**)&p_zn,    g_zn);
        cudaGetSymbolAddress((void**)&p_up,    g_up);
        cudaGetSymbolAddress((void**)&p_act,   g_act);
        cudaGetSymbolAddress((void**)&p_dwpad, g_dwpad);
        cudaGetSymbolAddress((void**)&p_wif,   g_wif_r);
        cudaGetSymbolAddress((void**)&p_wzo,   g_wzo_r);
        cudaGetSymbolAddress((void**)&p_upw,   g_upw_r);
        cudaFuncSetAttribute(gemm_mma<0>,
            cudaFuncAttributeMaxDynamicSharedMemorySize, GEMM_SMEM);
        cudaFuncSetAttribute(gemm_mma<1>,
            cudaFuncAttributeMaxDynamicSharedMemorySize, GEMM_SMEM);
        cudaFuncSetAttribute(gemm_mma<2>,
            cudaFuncAttributeMaxDynamicSharedMemorySize, GEMM_SMEM);
    }

    ln_kernel  <<<BT, 256>>>(x, ln_w, ln_b, p_xn);                                  // 1
    conv_kernel<<<(BT * DD + 255) / 256, 256>>>(p_xn, conv_w, conv_b, p_ifin);      // 2
    round_copy_kernel<<<(2048 * DD + 255) / 256, 256>>>(w_if, p_wif, 2048 * DD);    // 3
    round_copy_kernel<<<(2048 * DD + 255) / 256, 256>>>(w_zo, p_wzo, 2048 * DD);    // 4
    round_copy_kernel<<<(2730 * DD + 255) / 256, 256>>>(up_w, p_upw, 2730 * DD);    // 5
    gemm_mma<0><<<dim3(BT / 128, 2048 / 128), 256, GEMM_SMEM>>>(                    // 6
        p_ifin, p_wif, p_lif, BT, 2048, 1024, 1024, 1024, 2048, nullptr, nullptr);
    gemm_mma<0><<<dim3(BT / 128, 2048 / 128), 256, GEMM_SMEM>>>(                    // 7
        p_xn, p_wzo, p_lzo, BT, 2048, 1024, 1024, 1024, 2048, nullptr, nullptr);
    pad_dw_kernel<<<(DD * UPAD + 255) / 256, 256>>>(down_w, p_dwpad);               // 8
    scan_kernel<<<128, 256>>>(p_lif, p_lzo, w_hh, bias, gn_w, gn_b, p_zn);          // 9
    gemm_mma<1><<<dim3(BT / 128, (2730 + 127) / 128), 256, GEMM_SMEM>>>(            // 10
        p_zn, p_upw, p_up, BT, 2730, 1024, 1024, 1024, 2730, up_b, nullptr);
    act_kernel<<<(BT * UPAD + 255) / 256, 256>>>(p_up, p_act);                      // 11
    gemm_mma<2><<<dim3(BT / 128, 1024 / 128), 256, GEMM_SMEM>>>(                    // 12
        p_act, p_dwpad, out, BT, 1024, UPAD, UPAD, UPAD, 1024, down_b, x);
}